// round 15
// baseline (speedup 1.0000x reference)
#include <cuda_runtime.h>
#include <math.h>
#include <stdint.h>

#define BB 2
#define TT 2048
#define DD 1024
#define NHH 16
#define HDD 64
constexpr int BT = BB * TT;          // 4096 rows
constexpr int D3 = 3 * DD;           // 3072

// Scratch (no allocations allowed)
__device__ float g_qkv[BB * TT * D3];     // [B,T,3D] (tf32-rounded fp32)
__device__ float g_y[BB * TT * DD];       // [B,T,D]  (tf32-rounded fp32)
__device__ float g_xr[BB * TT * DD];      // x, tf32-rounded
__device__ float g_wqkvr[DD * D3];        // Wqkv, tf32-rounded
__device__ float g_wprojr[DD * DD];       // Wproj, tf32-rounded

// ---- helpers ----
__device__ __forceinline__ uint32_t f2tf32(float f) {
    uint32_t r; asm("cvt.rna.tf32.f32 %0, %1;" : "=r"(r) : "f"(f)); return r;
}
__device__ __forceinline__ void mma_tf32(float& d0, float& d1, float& d2, float& d3,
                                         uint32_t a0, uint32_t a1, uint32_t a2, uint32_t a3,
                                         uint32_t b0, uint32_t b1) {
    asm("mma.sync.aligned.m16n8k8.row.col.f32.tf32.tf32.f32 "
        "{%0,%1,%2,%3}, {%4,%5,%6,%7}, {%8,%9}, {%0,%1,%2,%3};"
        : "+f"(d0), "+f"(d1), "+f"(d2), "+f"(d3)
        : "r"(a0), "r"(a1), "r"(a2), "r"(a3), "r"(b0), "r"(b1));
}
__device__ __forceinline__ float ex2(float x) {
    float y; asm("ex2.approx.ftz.f32 %0, %1;" : "=f"(y) : "f"(x)); return y;
}

// ---------------------------------------------------------------------------
// Pre-round fp32 -> tf32-valued fp32 (element-wise, float4)
// ---------------------------------------------------------------------------
__global__ void round_tf32(const float* __restrict__ S, float* __restrict__ D, int n4)
{
    const int i = blockIdx.x * blockDim.x + threadIdx.x;
    if (i < n4) {
        float4 v = *(const float4*)(S + 4 * (size_t)i);
        uint4 u = make_uint4(f2tf32(v.x), f2tf32(v.y), f2tf32(v.z), f2tf32(v.w));
        *(uint4*)(D + 4 * (size_t)i) = u;
    }
}

// ---------------------------------------------------------------------------
// tf32 tensor-core GEMM: C = A @ B + bias.  Inputs pre-rounded to tf32.
// BM=BN=128, BK=16, 256 threads, 8 warps (2x4, 64x32 warp tile).
// Paired smem layout [ksq][m|n][kr] -> LDS.64 frag fetches; double-buffered.
// ROUND_OUT: round C to tf32 (when consumer feeds another tf32 mma).
// ---------------------------------------------------------------------------
constexpr int GP = 132;

template<bool ROUND_OUT>
__global__ __launch_bounds__(256, 2)
void gemm_tf32(const float* __restrict__ A, const float* __restrict__ Bm,
               const float* __restrict__ bias, float* __restrict__ C,
               int M, int N, int K)
{
    __shared__ uint32_t As2[2][8][GP][2];   // [stage][ksq][m][kr]
    __shared__ uint32_t Bs2[2][8][GP][2];   // [stage][ksq][n][kr]

    const int tid  = threadIdx.x;
    const int lane = tid & 31;
    const int wid  = tid >> 5;
    const int wm   = (wid >> 2) * 64;
    const int wn   = (wid & 3) * 32;
    const int m0 = blockIdx.y * 128;
    const int n0 = blockIdx.x * 128;
    const int kq = lane & 3;
    const int gq = lane >> 2;

    const int am = tid & 127;
    const int ah = tid >> 7;
    const float* Aptr = A + (size_t)(m0 + am) * K + ah * 4;

    const int kqb = (tid >> 5) & 3;
    const int kh  = tid >> 7;
    const int bc  = (tid & 31) * 4;
    const float* BptrL = Bm + (size_t)(kh * 8 + kqb) * N + n0 + bc;
    const float* BptrH = BptrL + (size_t)4 * N;

    uint4 ra0 = *(const uint4*)(Aptr);
    uint4 ra1 = *(const uint4*)(Aptr + 8);
    uint4 rb0 = *(const uint4*)(BptrL);
    uint4 rb1 = *(const uint4*)(BptrH);

    float acc[4][4][4];
    #pragma unroll
    for (int i = 0; i < 4; i++)
        #pragma unroll
        for (int j = 0; j < 4; j++)
            #pragma unroll
            for (int t = 0; t < 4; t++) acc[i][j][t] = 0.f;

    // store tile 0 into stage 0 (raw bit copies — inputs already tf32)
    {
        uint32_t a0v[4] = { ra0.x, ra0.y, ra0.z, ra0.w };
        uint32_t a1v[4] = { ra1.x, ra1.y, ra1.z, ra1.w };
        #pragma unroll
        for (int j = 0; j < 4; j++) {
            As2[0][j][am][ah]     = a0v[j];
            As2[0][4 + j][am][ah] = a1v[j];
        }
        uint4 u0 = make_uint4(rb0.x, rb1.x, rb0.y, rb1.y);
        uint4 u1 = make_uint4(rb0.z, rb1.z, rb0.w, rb1.w);
        *(uint4*)&Bs2[0][kh * 4 + kqb][bc][0]     = u0;
        *(uint4*)&Bs2[0][kh * 4 + kqb][bc + 2][0] = u1;
    }
    __syncthreads();

    for (int k0 = 0; k0 < K; k0 += 16) {
        const int st = (k0 >> 4) & 1;
        const bool more = (k0 + 16) < K;
        if (more) {
            ra0 = *(const uint4*)(Aptr + k0 + 16);
            ra1 = *(const uint4*)(Aptr + k0 + 24);
            rb0 = *(const uint4*)(BptrL + (size_t)(k0 + 16) * N);
            rb1 = *(const uint4*)(BptrH + (size_t)(k0 + 16) * N);
        }

        #pragma unroll
        for (int s = 0; s < 2; s++) {
            const int ksq = s * 4 + kq;
            uint32_t af[4][4], bf[4][2];
            #pragma unroll
            for (int i = 0; i < 4; i++) {
                uint2 alo = *(const uint2*)&As2[st][ksq][wm + 16 * i + gq][0];
                uint2 ahi = *(const uint2*)&As2[st][ksq][wm + 16 * i + gq + 8][0];
                af[i][0] = alo.x; af[i][1] = ahi.x; af[i][2] = alo.y; af[i][3] = ahi.y;
            }
            #pragma unroll
            for (int j = 0; j < 4; j++) {
                uint2 bp = *(const uint2*)&Bs2[st][ksq][wn + 8 * j + gq][0];
                bf[j][0] = bp.x; bf[j][1] = bp.y;
            }
            #pragma unroll
            for (int i = 0; i < 4; i++)
                #pragma unroll
                for (int j = 0; j < 4; j++)
                    mma_tf32(acc[i][j][0], acc[i][j][1], acc[i][j][2], acc[i][j][3],
                             af[i][0], af[i][1], af[i][2], af[i][3],
                             bf[j][0], bf[j][1]);
        }

        if (more) {
            const int st2 = st ^ 1;
            uint32_t a0v[4] = { ra0.x, ra0.y, ra0.z, ra0.w };
            uint32_t a1v[4] = { ra1.x, ra1.y, ra1.z, ra1.w };
            #pragma unroll
            for (int j = 0; j < 4; j++) {
                As2[st2][j][am][ah]     = a0v[j];
                As2[st2][4 + j][am][ah] = a1v[j];
            }
            uint4 u0 = make_uint4(rb0.x, rb1.x, rb0.y, rb1.y);
            uint4 u1 = make_uint4(rb0.z, rb1.z, rb0.w, rb1.w);
            *(uint4*)&Bs2[st2][kh * 4 + kqb][bc][0]     = u0;
            *(uint4*)&Bs2[st2][kh * 4 + kqb][bc + 2][0] = u1;
            __syncthreads();
        }
    }

    #pragma unroll
    for (int j = 0; j < 4; j++) {
        const int col = n0 + wn + j * 8 + 2 * kq;
        const float bi0 = bias[col];
        const float bi1 = bias[col + 1];
        #pragma unroll
        for (int i = 0; i < 4; i++) {
            const int row = m0 + wm + i * 16 + gq;
            float v00 = acc[i][j][0] + bi0, v01 = acc[i][j][1] + bi1;
            float v10 = acc[i][j][2] + bi0, v11 = acc[i][j][3] + bi1;
            if (ROUND_OUT) {
                v00 = __uint_as_float(f2tf32(v00));
                v01 = __uint_as_float(f2tf32(v01));
                v10 = __uint_as_float(f2tf32(v10));
                v11 = __uint_as_float(f2tf32(v11));
            }
            *(float2*)&C[(size_t)row * N + col]       = make_float2(v00, v01);
            *(float2*)&C[(size_t)(row + 8) * N + col] = make_float2(v10, v11);
        }
    }
}

// ---------------------------------------------------------------------------
// Tensor-core flash attention (tf32 mma.sync), causal. BQ=128, BKV=64.
// qkv is pre-rounded tf32 -> K/V staging is a raw bit copy (no cvt).
// Paired K/V smem layouts -> LDS.64 frag fetches. ex2-domain softmax.
// Epilogue writes g_y tf32-rounded (feeds proj GEMM).
// ---------------------------------------------------------------------------
constexpr int F_BQ  = 128;
constexpr int F_PST = 68;
constexpr int F_QST = 136;
constexpr int F_KP_W = 32 * 68 * 2;
constexpr int FLASH_SMEM = (2 * F_KP_W + F_BQ * F_PST) * 4;  // 69632 B
constexpr float QSCALE = 0.125f * 1.44269504088896f;

__global__ __launch_bounds__(256, 2) void flash_attn_tc()
{
    extern __shared__ float sm[];
    uint32_t* Kp = (uint32_t*)sm;          // [ksq=(d>>3)*4+(d&3)][kv][kr=(d>>2)&1]
    uint32_t* Vp = Kp + F_KP_W;            // [ksq=(kv>>3)*4+(kv&3)][d][kr=(kv>>2)&1]
    uint32_t* Ps = Vp + F_KP_W;            // [128][68] tf32 bits
    float*    Qt = (float*)Ps;             // staging alias [64][136] fp32

    const int tid  = threadIdx.x;
    const int lane = tid & 31;
    const int w    = tid >> 5;
    const int kq   = lane & 3;
    const int gq   = lane >> 2;
    const int qb   = gridDim.x - 1 - blockIdx.x;   // heavy blocks first
    const int q0   = qb * F_BQ;
    const int h    = blockIdx.y;
    const int b    = blockIdx.z;
    const int m0w  = w * 16;

    const float* qkv_b = g_qkv + (size_t)b * TT * D3;

    // ---- Q staging (scaled into log2 domain), transposed [d][q]
    {
        const int qr = tid & 127;
        const int dc = (tid >> 7) * 32;
        const float* qp = qkv_b + (size_t)(q0 + qr) * D3 + h * HDD + dc;
        #pragma unroll
        for (int c = 0; c < 8; c++) {
            float4 q4 = *(const float4*)(qp + 4 * c);
            Qt[(dc + 4 * c + 0) * F_QST + qr] = q4.x * QSCALE;
            Qt[(dc + 4 * c + 1) * F_QST + qr] = q4.y * QSCALE;
            Qt[(dc + 4 * c + 2) * F_QST + qr] = q4.z * QSCALE;
            Qt[(dc + 4 * c + 3) * F_QST + qr] = q4.w * QSCALE;
        }
    }
    __syncthreads();

    // ---- Q fragments -> registers (persist)
    uint32_t qf[8][4];
    #pragma unroll
    for (int ks = 0; ks < 8; ks++) {
        const int d0 = ks * 8 + kq;
        qf[ks][0] = f2tf32(Qt[d0 * F_QST + m0w + gq]);
        qf[ks][1] = f2tf32(Qt[d0 * F_QST + m0w + gq + 8]);
        qf[ks][2] = f2tf32(Qt[(d0 + 4) * F_QST + m0w + gq]);
        qf[ks][3] = f2tf32(Qt[(d0 + 4) * F_QST + m0w + gq + 8]);
    }
    __syncthreads();   // Qt now reusable as Ps

    float oacc[8][4];
    #pragma unroll
    for (int j = 0; j < 8; j++)
        #pragma unroll
        for (int t = 0; t < 4; t++) oacc[j][t] = 0.f;
    float m_r[2] = { -1e30f, -1e30f };
    float l_r[2] = { 0.f, 0.f };

    const int vrow = tid >> 2;
    const int vdc  = (tid & 3) * 16;
    const int vksq = (vrow >> 3) * 4 + (vrow & 3);
    const int vkr  = (vrow >> 2) & 1;
    const int krow = tid & 63;
    const int kdc  = (tid >> 6) * 16;

    const int nt = 2 * qb + 2;
    for (int it = 0; it < nt; it++) {
        __syncthreads();
        // ---- K (d-pairs) / V (kv-pairs): raw bit copies (qkv pre-rounded)
        {
            const uint32_t* kpg = (const uint32_t*)(qkv_b + (size_t)(it * 64 + krow) * D3
                                                    + DD + h * HDD + kdc);
            #pragma unroll
            for (int c = 0; c < 4; c++) {
                uint4 k4 = *(const uint4*)(kpg + 4 * c);
                const int db  = kdc + 4 * c;
                const int ksq = (db >> 3) * 4;
                const int kr  = (db >> 2) & 1;
                Kp[((ksq + 0) * 68 + krow) * 2 + kr] = k4.x;
                Kp[((ksq + 1) * 68 + krow) * 2 + kr] = k4.y;
                Kp[((ksq + 2) * 68 + krow) * 2 + kr] = k4.z;
                Kp[((ksq + 3) * 68 + krow) * 2 + kr] = k4.w;
            }
            const uint32_t* vpg = (const uint32_t*)(qkv_b + (size_t)(it * 64 + vrow) * D3
                                                    + 2 * DD + h * HDD + vdc);
            #pragma unroll
            for (int c = 0; c < 4; c++) {
                uint4 v4 = *(const uint4*)(vpg + 4 * c);
                const int d = vdc + 4 * c;
                Vp[(vksq * 68 + d + 0) * 2 + vkr] = v4.x;
                Vp[(vksq * 68 + d + 1) * 2 + vkr] = v4.y;
                Vp[(vksq * 68 + d + 2) * 2 + vkr] = v4.z;
                Vp[(vksq * 68 + d + 3) * 2 + vkr] = v4.w;
            }
        }
        __syncthreads();

        // ---- S = Q @ K^T
        float sacc[8][4];
        #pragma unroll
        for (int j = 0; j < 8; j++)
            #pragma unroll
            for (int t = 0; t < 4; t++) sacc[j][t] = 0.f;

        #pragma unroll
        for (int ks = 0; ks < 8; ks++) {
            const int row = ks * 4 + kq;
            #pragma unroll
            for (int j = 0; j < 8; j++) {
                uint2 kp2 = *(const uint2*)&Kp[(row * 68 + 8 * j + gq) * 2];
                mma_tf32(sacc[j][0], sacc[j][1], sacc[j][2], sacc[j][3],
                         qf[ks][0], qf[ks][1], qf[ks][2], qf[ks][3],
                         kp2.x, kp2.y);
            }
        }

        // ---- causal mask (diagonal-region tiles only)
        const int r0g = q0 + m0w + gq;
        const int r1g = r0g + 8;
        if (it >= nt - 2) {
            const int cb = it * 64 + 2 * kq;
            #pragma unroll
            for (int j = 0; j < 8; j++) {
                const int c = cb + j * 8;
                if (c     > r0g) sacc[j][0] = -1e30f;
                if (c + 1 > r0g) sacc[j][1] = -1e30f;
                if (c     > r1g) sacc[j][2] = -1e30f;
                if (c + 1 > r1g) sacc[j][3] = -1e30f;
            }
        }

        // ---- online softmax in log2 domain (quad reductions)
        float mx0 = -1e30f, mx1 = -1e30f;
        #pragma unroll
        for (int j = 0; j < 8; j++) {
            mx0 = fmaxf(mx0, fmaxf(sacc[j][0], sacc[j][1]));
            mx1 = fmaxf(mx1, fmaxf(sacc[j][2], sacc[j][3]));
        }
        mx0 = fmaxf(mx0, __shfl_xor_sync(0xffffffffu, mx0, 1));
        mx0 = fmaxf(mx0, __shfl_xor_sync(0xffffffffu, mx0, 2));
        mx1 = fmaxf(mx1, __shfl_xor_sync(0xffffffffu, mx1, 1));
        mx1 = fmaxf(mx1, __shfl_xor_sync(0xffffffffu, mx1, 2));

        const float mn0 = fmaxf(m_r[0], mx0);
        const float mn1 = fmaxf(m_r[1], mx1);
        const float al0 = ex2(m_r[0] - mn0);
        const float al1 = ex2(m_r[1] - mn1);

        float ps0 = 0.f, ps1 = 0.f;
        #pragma unroll
        for (int j = 0; j < 8; j++) {
            sacc[j][0] = ex2(sacc[j][0] - mn0);
            sacc[j][1] = ex2(sacc[j][1] - mn0);
            sacc[j][2] = ex2(sacc[j][2] - mn1);
            sacc[j][3] = ex2(sacc[j][3] - mn1);
            ps0 += sacc[j][0] + sacc[j][1];
            ps1 += sacc[j][2] + sacc[j][3];
        }
        ps0 += __shfl_xor_sync(0xffffffffu, ps0, 1);
        ps0 += __shfl_xor_sync(0xffffffffu, ps0, 2);
        ps1 += __shfl_xor_sync(0xffffffffu, ps1, 1);
        ps1 += __shfl_xor_sync(0xffffffffu, ps1, 2);

        l_r[0] = l_r[0] * al0 + ps0;  m_r[0] = mn0;
        l_r[1] = l_r[1] * al1 + ps1;  m_r[1] = mn1;
        #pragma unroll
        for (int j = 0; j < 8; j++) {
            oacc[j][0] *= al0;  oacc[j][1] *= al0;
            oacc[j][2] *= al1;  oacc[j][3] *= al1;
        }

        // ---- P -> smem (warp-local)
        #pragma unroll
        for (int j = 0; j < 8; j++) {
            uint2 p0 = make_uint2(f2tf32(sacc[j][0]), f2tf32(sacc[j][1]));
            uint2 p1 = make_uint2(f2tf32(sacc[j][2]), f2tf32(sacc[j][3]));
            *(uint2*)&Ps[(m0w + gq) * F_PST + j * 8 + 2 * kq]     = p0;
            *(uint2*)&Ps[(m0w + 8 + gq) * F_PST + j * 8 + 2 * kq] = p1;
        }
        __syncwarp();

        // ---- O += P @ V
        #pragma unroll
        for (int ks = 0; ks < 8; ks++) {
            const int kv0 = ks * 8 + kq;
            const int row = ks * 4 + kq;
            uint32_t pa0 = Ps[(m0w + gq) * F_PST + kv0];
            uint32_t pa1 = Ps[(m0w + 8 + gq) * F_PST + kv0];
            uint32_t pa2 = Ps[(m0w + gq) * F_PST + kv0 + 4];
            uint32_t pa3 = Ps[(m0w + 8 + gq) * F_PST + kv0 + 4];
            #pragma unroll
            for (int j = 0; j < 8; j++) {
                uint2 vp2 = *(const uint2*)&Vp[(row * 68 + 8 * j + gq) * 2];
                mma_tf32(oacc[j][0], oacc[j][1], oacc[j][2], oacc[j][3],
                         pa0, pa1, pa2, pa3, vp2.x, vp2.y);
            }
        }
    }

    // ---- epilogue: write y tf32-rounded (feeds proj GEMM as tf32 operand)
    const float inv0 = 1.f / l_r[0];
    const float inv1 = 1.f / l_r[1];
    const int r0g = q0 + m0w + gq;
    #pragma unroll
    for (int j = 0; j < 8; j++) {
        const int col = h * HDD + j * 8 + 2 * kq;
        uint2 v0 = make_uint2(f2tf32(oacc[j][0] * inv0), f2tf32(oacc[j][1] * inv0));
        uint2 v1 = make_uint2(f2tf32(oacc[j][2] * inv1), f2tf32(oacc[j][3] * inv1));
        *(uint2*)&g_y[(size_t)(b * TT + r0g) * DD + col]     = v0;
        *(uint2*)&g_y[(size_t)(b * TT + r0g + 8) * DD + col] = v1;
    }
}

// ---------------------------------------------------------------------------
extern "C" void kernel_launch(void* const* d_in, const int* in_sizes, int n_in,
                              void* d_out, int out_size)
{
    const float* x     = (const float*)d_in[0];
    const float* Wqkv  = (const float*)d_in[1];
    const float* bqkv  = (const float*)d_in[2];
    const float* Wproj = (const float*)d_in[3];
    const float* bproj = (const float*)d_in[4];
    float* out = (float*)d_out;

    float *qkv_ptr, *y_ptr, *xr, *wqkvr, *wprojr;
    cudaGetSymbolAddress((void**)&qkv_ptr, g_qkv);
    cudaGetSymbolAddress((void**)&y_ptr, g_y);
    cudaGetSymbolAddress((void**)&xr, g_xr);
    cudaGetSymbolAddress((void**)&wqkvr, g_wqkvr);
    cudaGetSymbolAddress((void**)&wprojr, g_wprojr);

    cudaFuncSetAttribute(flash_attn_tc, cudaFuncAttributeMaxDynamicSharedMemorySize, FLASH_SMEM);

    // 0) pre-round inputs to tf32 (removes all cvts from GEMM/flash hot loops)
    round_tf32<<<(BT * DD / 4 + 255) / 256, 256>>>(x, xr, BT * DD / 4);
    round_tf32<<<(DD * D3 / 4 + 255) / 256, 256>>>(Wqkv, wqkvr, DD * D3 / 4);
    round_tf32<<<(DD * DD / 4 + 255) / 256, 256>>>(Wproj, wprojr, DD * DD / 4);

    // 1) QKV = x @ Wqkv + bqkv  (output tf32-rounded; feeds flash)
    gemm_tf32<true><<<dim3(D3 / 128, BT / 128), 256>>>(xr, wqkvr, bqkv, qkv_ptr, BT, D3, DD);

    // 2) causal flash attention -> g_y (tf32-rounded)
    flash_attn_tc<<<dim3(TT / F_BQ, NHH, BB), 256, FLASH_SMEM>>>();

    // 3) out = y @ Wproj + bproj  (final output: NOT rounded)
    gemm_tf32<false><<<dim3(DD / 128, BT / 128), 256>>>(y_ptr, wprojr, bproj, out, BT, DD, DD);
}